// round 15
// baseline (speedup 1.0000x reference)
#include <cuda_runtime.h>
#include <cstdint>

// out[i, :] = embedding[index[i], :],  U=1M rows, D=64 f32 (256B/row), N=2M.
// Final configuration: contiguous per-block tile (2048 vectors = 128 rows),
// block's 128 indices staged once through shared memory (cuts idx LDGs 16x,
// idx->emb dependency via LDS), 8 independent front-batched float4 gathers
// per thread, contiguous 32KB store window per block.
//   emb : ld.global.cg  (L2-only)
//   out : __stcs        (evict-first streaming write)

static constexpr int UNROLL = 8;
static constexpr int THREADS = 256;
static constexpr int VECS_PER_BLOCK = THREADS * UNROLL;     // 2048
static constexpr int ROWS_PER_BLOCK = VECS_PER_BLOCK / 16;  // 128

__device__ __forceinline__ float4 ldcg4(const float4* p) {
    float4 v;
    asm("ld.global.cg.v4.f32 {%0,%1,%2,%3}, [%4];"
        : "=f"(v.x), "=f"(v.y), "=f"(v.z), "=f"(v.w)
        : "l"(p));
    return v;
}

__global__ __launch_bounds__(THREADS) void gather_kernel(
    const float4* __restrict__ emb,   // [U * 16] float4
    const int*    __restrict__ idx,   // [N]
    float4*       __restrict__ out,   // [N * 16] float4
    unsigned n_vec)                   // N * 16 = 2^25
{
    __shared__ int s_idx[ROWS_PER_BLOCK];

    const unsigned t = threadIdx.x;
    const unsigned vbase = blockIdx.x * VECS_PER_BLOCK;
    const unsigned rbase = vbase >> 4;

    // Stage this block's 128 indices (guard for non-exact shapes).
    if (t < ROWS_PER_BLOCK) {
        unsigned r = rbase + t;
        s_idx[t] = (r < (n_vec >> 4)) ? __ldg(&idx[r]) : 0;
    }
    __syncthreads();

    if (vbase + VECS_PER_BLOCK <= n_vec) {
        // Fast path: full tile, straight-line 8 independent gathers.
        int src[UNROLL];
#pragma unroll
        for (int u = 0; u < UNROLL; u++) {
            unsigned lv = u * THREADS + t;          // 0..2047
            src[u] = s_idx[lv >> 4];
        }
        float4 v[UNROLL];
#pragma unroll
        for (int u = 0; u < UNROLL; u++) {
            unsigned lv = u * THREADS + t;
            unsigned seg = lv & 15u;
            v[u] = ldcg4(&emb[((int64_t)src[u] << 4) + seg]);
        }
#pragma unroll
        for (int u = 0; u < UNROLL; u++) {
            __stcs(&out[vbase + u * THREADS + t], v[u]);
        }
    } else {
        // Tail tile (only if sizes aren't the expected exact fit).
#pragma unroll
        for (int u = 0; u < UNROLL; u++) {
            unsigned g = vbase + u * THREADS + t;
            if (g < n_vec) {
                int src = s_idx[(u * THREADS + t) >> 4];
                unsigned seg = g & 15u;
                float4 v = ldcg4(&emb[((int64_t)src << 4) + seg]);
                __stcs(&out[g], v);
            }
        }
    }
}

extern "C" void kernel_launch(void* const* d_in, const int* in_sizes, int n_in,
                              void* d_out, int out_size) {
    const float4* emb = (const float4*)d_in[0];  // embedding [U, 64] f32
    const int*    idx = (const int*)d_in[1];     // index [N] i32
    float4*       out = (float4*)d_out;

    int64_t n = in_sizes[1];                     // N = 2097152
    unsigned n_vec = (unsigned)(n * 16);         // 33,554,432

    unsigned blocks = (n_vec + VECS_PER_BLOCK - 1) / VECS_PER_BLOCK; // 16384
    gather_kernel<<<blocks, THREADS>>>(emb, idx, out, n_vec);
}